// round 10
// baseline (speedup 1.0000x reference)
#include <cuda_runtime.h>
#include <cuda_fp16.h>
#include <cstdint>

// Fused edge-MLP graph network. fp16 2-pass weights, double-buffered pipelined
// edge kernel (2 barriers/tile, register-prefetched gather). v10.
#define N_MAX 16384
#define SC    128
#define RED   32
#define PWN   32
#define PAIR  128
#define XDIM  96

#define TPB  256
#define ETPB 512
#define TS   128
#define PX   136     // fp16 element pitch of activation/weight planes

__device__ float g_t[(size_t)N_MAX * RED];
__device__ float g_tmp[(size_t)N_MAX * PAIR];

// ---------------------------------------------------------------------------
// helpers
// ---------------------------------------------------------------------------
__device__ __forceinline__ uint32_t smem_addr32(const void* p) {
    uint32_t a;
    asm("{ .reg .u64 t; cvta.to.shared.u64 t, %1; cvt.u32.u64 %0, t; }" : "=r"(a) : "l"(p));
    return a;
}
__device__ __forceinline__ void ldsm4(uint32_t& r0, uint32_t& r1, uint32_t& r2,
                                      uint32_t& r3, uint32_t addr) {
    asm volatile("ldmatrix.sync.aligned.m8n8.x4.shared.b16 {%0,%1,%2,%3}, [%4];"
                 : "=r"(r0), "=r"(r1), "=r"(r2), "=r"(r3) : "r"(addr));
}
__device__ __forceinline__ void hmma_f16(float* c, const uint32_t* a, const uint32_t* b) {
    asm volatile(
        "mma.sync.aligned.m16n8k16.row.col.f32.f16.f16.f32 "
        "{%0,%1,%2,%3}, {%4,%5,%6,%7}, {%8,%9}, {%0,%1,%2,%3};"
        : "+f"(c[0]), "+f"(c[1]), "+f"(c[2]), "+f"(c[3])
        : "r"(a[0]), "r"(a[1]), "r"(a[2]), "r"(a[3]), "r"(b[0]), "r"(b[1]));
}
__device__ __forceinline__ uint16_t f2h(float x) {
    __half h = __float2half_rn(x);
    return *(uint16_t*)&h;
}
__device__ __forceinline__ void hilo_h(float x, uint16_t& h, uint16_t& l) {
    __half hb = __float2half_rn(x);
    __half lb = __float2half_rn(x - __half2float(hb));
    h = *(uint16_t*)&hb;
    l = *(uint16_t*)&lb;
}
__device__ __forceinline__ uint32_t pk2(uint16_t a, uint16_t b) {
    return (uint32_t)a | ((uint32_t)b << 16);
}

// ---------------------------------------------------------------------------
__global__ void clear_accum_kernel(int total) {
    int i = blockIdx.x * blockDim.x + threadIdx.x;
    if (i < total) g_tmp[i] = 0.0f;
}

// ---------------------------------------------------------------------------
// Kernel 1: t = relu(infeats @ W_rd + b_rd)
// ---------------------------------------------------------------------------
__global__ __launch_bounds__(TPB, 1)
void reduce_kernel(const float* __restrict__ infeats,
                   const float* __restrict__ W_rd,
                   const float* __restrict__ b_rd, int N) {
    __shared__ float Ws[SC * RED];
    __shared__ float rows[8 * SC];
    const int tid = threadIdx.x;
    const int base = blockIdx.x * 8;
    for (int i = tid; i < SC * RED; i += TPB) Ws[i] = W_rd[i];
    for (int i = tid; i < 8 * SC; i += TPB) {
        int nl = i >> 7, k = i & 127;
        rows[i] = (base + nl < N) ? infeats[(size_t)(base + nl) * SC + k] : 0.0f;
    }
    __syncthreads();
    const int nl = tid >> 5, r = tid & 31;
    float acc = b_rd[r];
#pragma unroll 8
    for (int i = 0; i < SC; i++) acc += rows[nl * SC + i] * Ws[i * RED + r];
    if (base + nl < N) g_t[(size_t)(base + nl) * RED + r] = fmaxf(acc, 0.0f);
}

// ---------------------------------------------------------------------------
// Kernel 2: pipelined fused edge MLP + scatter-max. 512 threads / 16 warps.
// ---------------------------------------------------------------------------
#define PLANE_B (128 * PX * 2)   // 34816 bytes per fp16 plane
#define OFF_XA  0
#define OFF_XB  (OFF_XA + PLANE_B)
#define OFF_W0H (OFF_XB + PLANE_B)
#define OFF_W0L (OFF_W0H + PLANE_B)
#define OFF_W1H (OFF_W0L + PLANE_B)
#define OFF_W1L (OFF_W1H + PLANE_B)
#define OFF_CS  (OFF_W1L + PLANE_B)   // cs[2][128]
#define OFF_B0  (OFF_CS + 1024)
#define OFF_B1  (OFF_B0 + 512)
#define EDGE_SMEM_BYTES (OFF_B1 + 512)

struct LaneMap { int a_row, a_col, b_row, b_col; };

// 2-pass GEMM strip: acc += A * (Wh + Wl)
template <int KS>
__device__ __forceinline__ void gemm_strip(uint32_t x,
                                           uint32_t wh, uint32_t wl,
                                           int wrow, int wcol, LaneMap lm,
                                           float acc[2][4][4]) {
#pragma unroll
    for (int m = 0; m < 2; m++)
#pragma unroll
        for (int n = 0; n < 4; n++)
#pragma unroll
            for (int i = 0; i < 4; i++) acc[m][n][i] = 0.f;

#pragma unroll 2
    for (int ks = 0; ks < KS; ks++) {
        const int k0 = ks * 16;
        uint32_t A[2][4];
#pragma unroll
        for (int m = 0; m < 2; m++) {
            uint32_t off = (uint32_t)((wrow + m * 16 + lm.a_row) * PX + k0 + lm.a_col) * 2;
            ldsm4(A[m][0], A[m][1], A[m][2], A[m][3], x + off);
        }
        uint32_t Bh[4][2], Bl[4][2];
#pragma unroll
        for (int nn = 0; nn < 2; nn++) {
            uint32_t off = (uint32_t)((wcol + nn * 16 + lm.b_row) * PX + k0 + lm.b_col) * 2;
            uint32_t r0, r1, r2, r3;
            ldsm4(r0, r1, r2, r3, wh + off);
            Bh[nn * 2][0] = r0;     Bh[nn * 2][1] = r1;
            Bh[nn * 2 + 1][0] = r2; Bh[nn * 2 + 1][1] = r3;
            ldsm4(r0, r1, r2, r3, wl + off);
            Bl[nn * 2][0] = r0;     Bl[nn * 2][1] = r1;
            Bl[nn * 2 + 1][0] = r2; Bl[nn * 2 + 1][1] = r3;
        }
#pragma unroll
        for (int m = 0; m < 2; m++)
#pragma unroll
            for (int n = 0; n < 4; n++) {
                hmma_f16(acc[m][n], A[m], Bh[n]);
                hmma_f16(acc[m][n], A[m], Bl[n]);
            }
    }
}

// per-thread gather of 6 float4 groups for one tile into registers
__device__ __forceinline__ void gather_regs(const float* __restrict__ pw,
                                            const int* __restrict__ c_idx,
                                            const int* __restrict__ n_idx,
                                            int tbase, int pnv, int tid,
                                            float4 pf[6]) {
#pragma unroll
    for (int j = 0; j < 6; j++) {
        int i = tid + j * ETPB;
        int r = i / 24, gg = i - r * 24;
        float4 v = make_float4(0.f, 0.f, 0.f, 0.f);
        if (r < pnv) {
            if (gg < 8) {
                v = *(const float4*)&pw[(size_t)(tbase + r) * PWN + gg * 4];
            } else {
                int c = c_idx[tbase + r];
                if (gg < 16) {
                    v = *(const float4*)&g_t[(size_t)c * RED + (gg - 8) * 4];
                } else {
                    int n = n_idx[tbase + r];
                    if (n != c) v = *(const float4*)&g_t[(size_t)n * RED + (gg - 16) * 4];
                }
            }
        }
        pf[j] = v;
    }
}

__device__ __forceinline__ void store_gather(char* smem, int xoffb,
                                             int tid, const float4 pf[6]) {
#pragma unroll
    for (int j = 0; j < 6; j++) {
        int i = tid + j * ETPB;
        int r = i / 24, gg = i - r * 24;
        uint32_t o = (uint32_t)(r * PX + gg * 4) * 2;
        *(uint2*)(smem + xoffb + o) =
            make_uint2(pk2(f2h(pf[j].x), f2h(pf[j].y)), pk2(f2h(pf[j].z), f2h(pf[j].w)));
    }
}

__global__ __launch_bounds__(ETPB, 1)
void edge_kernel(const float* __restrict__ pw,
                 const int* __restrict__ c_idx,
                 const int* __restrict__ n_idx,
                 const float* __restrict__ W0, const float* __restrict__ b0,
                 const float* __restrict__ W1, const float* __restrict__ b1,
                 int E, int ntiles) {
    extern __shared__ char smem[];
    const uint32_t sb  = smem_addr32(smem);
    const uint32_t w0h = sb + OFF_W0H, w0l = sb + OFF_W0L;
    const uint32_t w1h = sb + OFF_W1H, w1l = sb + OFF_W1L;
    int*   csb = (int*)(smem + OFF_CS);    // [2][128]
    float* b0s = (float*)(smem + OFF_B0);
    float* b1s = (float*)(smem + OFF_B1);

    const int tid = threadIdx.x;
    const int wid = tid >> 5, lid = tid & 31;
    const int wrow = (wid & 3) * 32;
    const int wcol = (wid >> 2) * 32;
    const int g = lid >> 2, t = lid & 3;

    LaneMap lm;
    lm.a_row = (lid & 7) + ((lid >> 3) & 1) * 8;
    lm.a_col = ((lid >> 4) & 1) * 8;
    lm.b_row = (lid & 7) + ((lid >> 4) & 1) * 8;
    lm.b_col = ((lid >> 3) & 1) * 8;

    // weights: transpose W[k][j] -> planes[j][k], fp16 hi/lo split
    for (int idx = tid; idx < XDIM * PAIR; idx += ETPB) {
        int k = idx >> 7, j = idx & 127;
        uint16_t h, l; hilo_h(W0[idx], h, l);
        uint32_t o = (uint32_t)(j * PX + k) * 2;
        *(uint16_t*)(smem + OFF_W0H + o) = h;
        *(uint16_t*)(smem + OFF_W0L + o) = l;
    }
    for (int idx = tid; idx < PAIR * PAIR; idx += ETPB) {
        int k = idx >> 7, j = idx & 127;
        uint16_t h, l; hilo_h(W1[idx], h, l);
        uint32_t o = (uint32_t)(j * PX + k) * 2;
        *(uint16_t*)(smem + OFF_W1H + o) = h;
        *(uint16_t*)(smem + OFF_W1L + o) = l;
    }
    if (tid < PAIR) { b0s[tid] = b0[tid]; b1s[tid] = b1[tid]; }

    const int tile0 = blockIdx.x;
    if (tile0 >= ntiles) return;   // (ntiles >= grid in practice)

    // prologue: gather + store tile0 into plane A (parity 0)
    {
        int tbase = tile0 * TS;
        int pnv = min(TS, E - tbase);
        float4 pf[6];
        gather_regs(pw, c_idx, n_idx, tbase, pnv, tid, pf);
        store_gather(smem, OFF_XA, tid, pf);
        if (tid < TS) csb[tid] = (tid < pnv) ? c_idx[tbase + tid] : -1;
    }
    __syncthreads();

    int p = 0;
    for (int tile = tile0; tile < ntiles; tile += gridDim.x, p ^= 1) {
        const uint32_t xcur = sb + OFF_XA + p * PLANE_B;
        const int xnextb = OFF_XA + (1 - p) * PLANE_B;
        int* cs_cur = csb + p * TS;
        int* cs_nxt = csb + (1 - p) * TS;

        // prefetch next tile's gather into registers (hidden under GEMM1)
        const int ntile = tile + gridDim.x;
        const bool pvalid = ntile < ntiles;
        int nbase = 0, pnv = 0;
        float4 pf[6];
        if (pvalid) {
            nbase = ntile * TS;
            pnv = min(TS, E - nbase);
            gather_regs(pw, c_idx, n_idx, nbase, pnv, tid, pf);
        }

        // GEMM1: K = 96 on X(tile)
        float acc[2][4][4];
        gemm_strip<6>(xcur, w0h, w0l, wrow, wcol, lm, acc);
        __syncthreads();   // all X(tile) reads complete

        // epilogue 1: relu(acc+b0) -> fp16 -> H1 (overwrite current plane)
#pragma unroll
        for (int m = 0; m < 2; m++) {
            const int r0 = wrow + m * 16 + g;
#pragma unroll
            for (int n = 0; n < 4; n++) {
                const int col = wcol + n * 8 + t * 2;
                const float bx = b0s[col], by = b0s[col + 1];
                float v0 = fmaxf(acc[m][n][0] + bx, 0.f);
                float v1 = fmaxf(acc[m][n][1] + by, 0.f);
                float v2 = fmaxf(acc[m][n][2] + bx, 0.f);
                float v3 = fmaxf(acc[m][n][3] + by, 0.f);
                uint32_t o0 = (uint32_t)(r0 * PX + col) * 2;
                uint32_t o1 = (uint32_t)((r0 + 8) * PX + col) * 2;
                *(uint32_t*)((char*)smem + OFF_XA + p * PLANE_B + o0) = pk2(f2h(v0), f2h(v1));
                *(uint32_t*)((char*)smem + OFF_XA + p * PLANE_B + o1) = pk2(f2h(v2), f2h(v3));
            }
        }
        // store prefetched gather into the other plane
        if (pvalid) {
            store_gather(smem, xnextb, tid, pf);
            if (tid < TS) cs_nxt[tid] = (tid < pnv) ? c_idx[nbase + tid] : -1;
        }
        __syncthreads();   // H1 visible; next X plane ready

        // GEMM2: K = 128 on H1
        gemm_strip<8>(xcur, w1h, w1l, wrow, wcol, lm, acc);

        // epilogue 2: relu(acc+b1) -> scatter atomicMax (values >= 0)
#pragma unroll
        for (int m = 0; m < 2; m++) {
            const int r0 = wrow + m * 16 + g;
            const int e0 = cs_cur[r0], e1 = cs_cur[r0 + 8];
#pragma unroll
            for (int n = 0; n < 4; n++) {
                const int col = wcol + n * 8 + t * 2;
                const float bx = b1s[col], by = b1s[col + 1];
                if (e0 >= 0) {
                    float v0 = acc[m][n][0] + bx;
                    float v1 = acc[m][n][1] + by;
                    float* dst = &g_tmp[(size_t)e0 * PAIR + col];
                    if (v0 > 0.f) atomicMax((int*)&dst[0], __float_as_int(v0));
                    if (v1 > 0.f) atomicMax((int*)&dst[1], __float_as_int(v1));
                }
                if (e1 >= 0) {
                    float v2 = acc[m][n][2] + bx;
                    float v3 = acc[m][n][3] + by;
                    float* dst = &g_tmp[(size_t)e1 * PAIR + col];
                    if (v2 > 0.f) atomicMax((int*)&dst[0], __float_as_int(v2));
                    if (v3 > 0.f) atomicMax((int*)&dst[1], __float_as_int(v3));
                }
            }
        }
        // no barrier: next iteration's writes (after its sync#1) can't race
    }
}

// ---------------------------------------------------------------------------
// Kernel 3: node MLP, 64-node tiles, 256 threads, per-layer weight staging.
// (R8 configuration — measured 80.3us; the all-preload variant regressed.)
// ---------------------------------------------------------------------------
#define NTS 64
#define ACT_LD 132
#define NODE_SMEM_BYTES ((NTS*ACT_LD + PAIR*PAIR) * 4)

__global__ __launch_bounds__(TPB, 1)
void node_kernel(const float* __restrict__ infeats,
                 const float* __restrict__ Wa, const float* __restrict__ ba,
                 const float* __restrict__ Wb, const float* __restrict__ bb_,
                 const float* __restrict__ W2, const float* __restrict__ b2,
                 float* __restrict__ out, int N) {
    extern __shared__ float smemf[];
    float* acts = smemf;                 // 64 x 132
    float* Ws   = smemf + NTS * ACT_LD;  // 128 x 128

    const int tid = threadIdx.x;
    const int base = blockIdx.x * NTS;
    const int nvalid = min(NTS, N - base);

    for (int idx = tid; idx < NTS * (PAIR / 4); idx += TPB) {
        int node = idx >> 5, k = (idx & 31) * 4;
        float4 v = make_float4(0.f, 0.f, 0.f, 0.f);
        if (node < nvalid) v = *(const float4*)&g_tmp[(size_t)(base + node) * PAIR + k];
        *(float4*)&acts[node * ACT_LD + k] = v;
    }

    const int tx = tid & 15, ty = tid >> 4;
    const int col0 = tx * 8, row0 = ty * 4;

    const float* Wp[3] = {Wa, Wb, W2};
    const float* bp[3] = {ba, bb_, b2};

    for (int layer = 0; layer < 3; layer++) {
        __syncthreads();
        for (int i = tid * 4; i < PAIR * PAIR; i += TPB * 4)
            *(float4*)&Ws[i] = *(const float4*)&Wp[layer][i];
        __syncthreads();

        float acc[4][8];
#pragma unroll
        for (int r = 0; r < 4; r++)
#pragma unroll
            for (int c = 0; c < 8; c++) acc[r][c] = 0.f;

        for (int k = 0; k < PAIR; k += 4) {
            float4 a[4];
#pragma unroll
            for (int r = 0; r < 4; r++)
                a[r] = *(float4*)&acts[(row0 + r) * ACT_LD + k];
#pragma unroll
            for (int kk = 0; kk < 4; kk++) {
                float4 w0 = *(float4*)&Ws[(k + kk) * PAIR + col0];
                float4 w1 = *(float4*)&Ws[(k + kk) * PAIR + col0 + 4];
                float b[8] = {w0.x, w0.y, w0.z, w0.w, w1.x, w1.y, w1.z, w1.w};
#pragma unroll
                for (int r = 0; r < 4; r++) {
                    float av = (kk == 0) ? a[r].x : (kk == 1) ? a[r].y
                             : (kk == 2) ? a[r].z : a[r].w;
#pragma unroll
                    for (int c = 0; c < 8; c++) acc[r][c] += av * b[c];
                }
            }
        }
        __syncthreads();

        float bias[8];
#pragma unroll
        for (int c = 0; c < 8; c++) bias[c] = bp[layer][col0 + c];

        if (layer < 2) {
#pragma unroll
            for (int r = 0; r < 4; r++) {
                float4 v0, v1;
                v0.x = fmaxf(acc[r][0] + bias[0], 0.f);
                v0.y = fmaxf(acc[r][1] + bias[1], 0.f);
                v0.z = fmaxf(acc[r][2] + bias[2], 0.f);
                v0.w = fmaxf(acc[r][3] + bias[3], 0.f);
                v1.x = fmaxf(acc[r][4] + bias[4], 0.f);
                v1.y = fmaxf(acc[r][5] + bias[5], 0.f);
                v1.z = fmaxf(acc[r][6] + bias[6], 0.f);
                v1.w = fmaxf(acc[r][7] + bias[7], 0.f);
                *(float4*)&acts[(row0 + r) * ACT_LD + col0]     = v0;
                *(float4*)&acts[(row0 + r) * ACT_LD + col0 + 4] = v1;
            }
        } else {
#pragma unroll
            for (int r = 0; r < 4; r++) {
                int node = row0 + r;
                if (node < nvalid) {
                    const float* inrow = &infeats[(size_t)(base + node) * SC + col0];
                    float* orow = &out[(size_t)(base + node) * SC + col0];
                    float4 i0 = *(const float4*)&inrow[0];
                    float4 i1 = *(const float4*)&inrow[4];
                    float4 v0, v1;
                    v0.x = fmaxf(acc[r][0] + bias[0] + i0.x, 0.f);
                    v0.y = fmaxf(acc[r][1] + bias[1] + i0.y, 0.f);
                    v0.z = fmaxf(acc[r][2] + bias[2] + i0.z, 0.f);
                    v0.w = fmaxf(acc[r][3] + bias[3] + i0.w, 0.f);
                    v1.x = fmaxf(acc[r][4] + bias[4] + i1.x, 0.f);
                    v1.y = fmaxf(acc[r][5] + bias[5] + i1.y, 0.f);
                    v1.z = fmaxf(acc[r][6] + bias[6] + i1.z, 0.f);
                    v1.w = fmaxf(acc[r][7] + bias[7] + i1.w, 0.f);
                    *(float4*)&orow[0] = v0;
                    *(float4*)&orow[4] = v1;
                }
            }
        }
    }
}

// ---------------------------------------------------------------------------
extern "C" void kernel_launch(void* const* d_in, const int* in_sizes, int n_in,
                              void* d_out, int out_size) {
    const float* infeats = (const float*)d_in[0];
    const float* pw      = (const float*)d_in[1];
    const int*   c_idxs  = (const int*)d_in[2];
    const int*   n_idxs  = (const int*)d_in[3];
    const float* W_rd  = (const float*)d_in[5];
    const float* b_rd  = (const float*)d_in[6];
    const float* W_pw0 = (const float*)d_in[7];
    const float* b_pw0 = (const float*)d_in[8];
    const float* W_pw1 = (const float*)d_in[9];
    const float* b_pw1 = (const float*)d_in[10];
    const float* W_f1a = (const float*)d_in[11];
    const float* b_f1a = (const float*)d_in[12];
    const float* W_f1b = (const float*)d_in[13];
    const float* b_f1b = (const float*)d_in[14];
    const float* W_f2  = (const float*)d_in[15];
    const float* b_f2  = (const float*)d_in[16];
    float* out = (float*)d_out;

    const int N = in_sizes[0] / SC;
    const int E = in_sizes[1] / PWN;

    cudaFuncSetAttribute(edge_kernel, cudaFuncAttributeMaxDynamicSharedMemorySize,
                         EDGE_SMEM_BYTES);
    cudaFuncSetAttribute(node_kernel, cudaFuncAttributeMaxDynamicSharedMemorySize,
                         NODE_SMEM_BYTES);

    const int tot = N * PAIR;
    clear_accum_kernel<<<(tot + 255) / 256, 256>>>(tot);

    reduce_kernel<<<(N + 7) / 8, TPB>>>(infeats, W_rd, b_rd, N);

    const int ntiles = (E + TS - 1) / TS;
    const int grid = ntiles < 148 ? ntiles : 148;
    edge_kernel<<<grid, ETPB, EDGE_SMEM_BYTES>>>(pw, c_idxs, n_idxs,
                                                 W_pw0, b_pw0, W_pw1, b_pw1,
                                                 E, ntiles);

    node_kernel<<<(N + NTS - 1) / NTS, TPB, NODE_SMEM_BYTES>>>(
        infeats, W_f1a, b_f1a, W_f1b, b_f1b, W_f2, b_f2, out, N);
}

// round 11
// speedup vs baseline: 1.1761x; 1.1761x over previous
#include <cuda_runtime.h>
#include <cuda_fp16.h>
#include <cstdint>

// Fused edge-MLP graph network. fp16 single-pass weights (R9 structure). v11.
#define N_MAX 16384
#define SC    128
#define RED   32
#define PWN   32
#define PAIR  128
#define XDIM  96

#define TPB  256
#define ETPB 512
#define TS   128
#define PX   136     // fp16 element pitch of activation/weight planes

__device__ float g_t[(size_t)N_MAX * RED];
__device__ float g_tmp[(size_t)N_MAX * PAIR];

// ---------------------------------------------------------------------------
// helpers
// ---------------------------------------------------------------------------
__device__ __forceinline__ uint32_t smem_addr32(const void* p) {
    uint32_t a;
    asm("{ .reg .u64 t; cvta.to.shared.u64 t, %1; cvt.u32.u64 %0, t; }" : "=r"(a) : "l"(p));
    return a;
}
__device__ __forceinline__ void ldsm4(uint32_t& r0, uint32_t& r1, uint32_t& r2,
                                      uint32_t& r3, uint32_t addr) {
    asm volatile("ldmatrix.sync.aligned.m8n8.x4.shared.b16 {%0,%1,%2,%3}, [%4];"
                 : "=r"(r0), "=r"(r1), "=r"(r2), "=r"(r3) : "r"(addr));
}
__device__ __forceinline__ void hmma_f16(float* c, const uint32_t* a, const uint32_t* b) {
    asm volatile(
        "mma.sync.aligned.m16n8k16.row.col.f32.f16.f16.f32 "
        "{%0,%1,%2,%3}, {%4,%5,%6,%7}, {%8,%9}, {%0,%1,%2,%3};"
        : "+f"(c[0]), "+f"(c[1]), "+f"(c[2]), "+f"(c[3])
        : "r"(a[0]), "r"(a[1]), "r"(a[2]), "r"(a[3]), "r"(b[0]), "r"(b[1]));
}
__device__ __forceinline__ uint16_t f2h(float x) {
    __half h = __float2half_rn(x);
    return *(uint16_t*)&h;
}
__device__ __forceinline__ uint32_t pk2(uint16_t a, uint16_t b) {
    return (uint32_t)a | ((uint32_t)b << 16);
}

// ---------------------------------------------------------------------------
__global__ void clear_accum_kernel(int total) {
    int i = blockIdx.x * blockDim.x + threadIdx.x;
    if (i < total) g_tmp[i] = 0.0f;
}

// ---------------------------------------------------------------------------
// Kernel 1: t = relu(infeats @ W_rd + b_rd)
// ---------------------------------------------------------------------------
__global__ __launch_bounds__(TPB, 1)
void reduce_kernel(const float* __restrict__ infeats,
                   const float* __restrict__ W_rd,
                   const float* __restrict__ b_rd, int N) {
    __shared__ float Ws[SC * RED];
    __shared__ float rows[8 * SC];
    const int tid = threadIdx.x;
    const int base = blockIdx.x * 8;
    for (int i = tid; i < SC * RED; i += TPB) Ws[i] = W_rd[i];
    for (int i = tid; i < 8 * SC; i += TPB) {
        int nl = i >> 7, k = i & 127;
        rows[i] = (base + nl < N) ? infeats[(size_t)(base + nl) * SC + k] : 0.0f;
    }
    __syncthreads();
    const int nl = tid >> 5, r = tid & 31;
    float acc = b_rd[r];
#pragma unroll 8
    for (int i = 0; i < SC; i++) acc += rows[nl * SC + i] * Ws[i * RED + r];
    if (base + nl < N) g_t[(size_t)(base + nl) * RED + r] = fmaxf(acc, 0.0f);
}

// ---------------------------------------------------------------------------
// Kernel 2: fused edge MLP (mma.sync fp16 single-pass) + scatter-max.
// 512 threads / 16 warps; warp strip = 32 rows x 32 cols.
// ---------------------------------------------------------------------------
#define PLANE_B (128 * PX * 2)   // 34816 bytes per fp16 plane
#define OFF_X   0
#define OFF_W0  (OFF_X + PLANE_B)
#define OFF_W1  (OFF_W0 + PLANE_B)
#define OFF_CS  (OFF_W1 + PLANE_B)
#define OFF_NS  (OFF_CS + 512)
#define OFF_B0  (OFF_NS + 512)
#define OFF_B1  (OFF_B0 + 512)
#define EDGE_SMEM_BYTES (OFF_B1 + 512)

struct LaneMap { int a_row, a_col, b_row, b_col; };

// single-pass GEMM strip: acc += A * W
template <int KS>
__device__ __forceinline__ void gemm_strip(uint32_t x, uint32_t w,
                                           int wrow, int wcol, LaneMap lm,
                                           float acc[2][4][4]) {
#pragma unroll
    for (int m = 0; m < 2; m++)
#pragma unroll
        for (int n = 0; n < 4; n++)
#pragma unroll
            for (int i = 0; i < 4; i++) acc[m][n][i] = 0.f;

#pragma unroll 2
    for (int ks = 0; ks < KS; ks++) {
        const int k0 = ks * 16;
        uint32_t A[2][4];
#pragma unroll
        for (int m = 0; m < 2; m++) {
            uint32_t off = (uint32_t)((wrow + m * 16 + lm.a_row) * PX + k0 + lm.a_col) * 2;
            ldsm4(A[m][0], A[m][1], A[m][2], A[m][3], x + off);
        }
        uint32_t B[4][2];
#pragma unroll
        for (int nn = 0; nn < 2; nn++) {
            uint32_t off = (uint32_t)((wcol + nn * 16 + lm.b_row) * PX + k0 + lm.b_col) * 2;
            uint32_t r0, r1, r2, r3;
            ldsm4(r0, r1, r2, r3, w + off);
            B[nn * 2][0] = r0;     B[nn * 2][1] = r1;
            B[nn * 2 + 1][0] = r2; B[nn * 2 + 1][1] = r3;
        }
#pragma unroll
        for (int m = 0; m < 2; m++)
#pragma unroll
            for (int n = 0; n < 4; n++)
                hmma_f16(acc[m][n], A[m], B[n]);
    }
}

__global__ __launch_bounds__(ETPB, 1)
void edge_kernel(const float* __restrict__ pw,
                 const int* __restrict__ c_idx,
                 const int* __restrict__ n_idx,
                 const float* __restrict__ W0, const float* __restrict__ b0,
                 const float* __restrict__ W1, const float* __restrict__ b1,
                 int E, int ntiles) {
    extern __shared__ char smem[];
    const uint32_t sb = smem_addr32(smem);
    const uint32_t x  = sb + OFF_X;
    const uint32_t w0 = sb + OFF_W0;
    const uint32_t w1 = sb + OFF_W1;
    int*   cs  = (int*)(smem + OFF_CS);
    int*   ns  = (int*)(smem + OFF_NS);
    float* b0s = (float*)(smem + OFF_B0);
    float* b1s = (float*)(smem + OFF_B1);

    const int tid = threadIdx.x;
    const int wid = tid >> 5, lid = tid & 31;
    const int wrow = (wid & 3) * 32;
    const int wcol = (wid >> 2) * 32;
    const int g = lid >> 2, t = lid & 3;

    LaneMap lm;
    lm.a_row = (lid & 7) + ((lid >> 3) & 1) * 8;
    lm.a_col = ((lid >> 4) & 1) * 8;
    lm.b_row = (lid & 7) + ((lid >> 4) & 1) * 8;
    lm.b_col = ((lid >> 3) & 1) * 8;

    // weights: transpose W[k][j] -> plane[j][k], single fp16
    for (int idx = tid; idx < XDIM * PAIR; idx += ETPB) {
        int k = idx >> 7, j = idx & 127;
        *(uint16_t*)(smem + OFF_W0 + (uint32_t)(j * PX + k) * 2) = f2h(W0[idx]);
    }
    for (int idx = tid; idx < PAIR * PAIR; idx += ETPB) {
        int k = idx >> 7, j = idx & 127;
        *(uint16_t*)(smem + OFF_W1 + (uint32_t)(j * PX + k) * 2) = f2h(W1[idx]);
    }
    if (tid < PAIR) { b0s[tid] = b0[tid]; b1s[tid] = b1[tid]; }

    for (int tile = blockIdx.x; tile < ntiles; tile += gridDim.x) {
        const int base = tile * TS;
        const int nvalid = min(TS, E - base);
        __syncthreads();   // previous tile fully consumed
        if (tid < TS) {
            bool ok = tid < nvalid;
            cs[tid] = ok ? c_idx[base + tid] : -1;
            ns[tid] = ok ? n_idx[base + tid] : -1;
        }
        __syncthreads();

        // gather X rows (edges), cols 0..95, fp16 single plane
        for (int idx = tid; idx < TS * 24; idx += ETPB) {
            int r = idx / 24, gg = idx - r * 24;
            float4 v = make_float4(0.f, 0.f, 0.f, 0.f);
            if (r < nvalid) {
                if (gg < 8) {
                    v = *(const float4*)&pw[(size_t)(base + r) * PWN + gg * 4];
                } else {
                    int c = cs[r], n = ns[r];
                    if (gg < 16) v = *(const float4*)&g_t[(size_t)c * RED + (gg - 8) * 4];
                    else if (n != c) v = *(const float4*)&g_t[(size_t)n * RED + (gg - 16) * 4];
                }
            }
            uint32_t o = (uint32_t)(r * PX + gg * 4) * 2;
            *(uint2*)(smem + OFF_X + o) =
                make_uint2(pk2(f2h(v.x), f2h(v.y)), pk2(f2h(v.z), f2h(v.w)));
        }
        __syncthreads();

        // GEMM1: K = 96
        float acc[2][4][4];
        gemm_strip<6>(x, w0, wrow, wcol, lm, acc);
        __syncthreads();   // X reads complete before H1 overwrite

        // epilogue 1: relu(acc+b0) -> fp16 -> H1 plane (in place of X)
#pragma unroll
        for (int m = 0; m < 2; m++) {
            const int r0 = wrow + m * 16 + g;
#pragma unroll
            for (int n = 0; n < 4; n++) {
                const int col = wcol + n * 8 + t * 2;
                const float bx = b0s[col], by = b0s[col + 1];
                float v0 = fmaxf(acc[m][n][0] + bx, 0.f);
                float v1 = fmaxf(acc[m][n][1] + by, 0.f);
                float v2 = fmaxf(acc[m][n][2] + bx, 0.f);
                float v3 = fmaxf(acc[m][n][3] + by, 0.f);
                uint32_t o0 = (uint32_t)(r0 * PX + col) * 2;
                uint32_t o1 = (uint32_t)((r0 + 8) * PX + col) * 2;
                *(uint32_t*)(smem + OFF_X + o0) = pk2(f2h(v0), f2h(v1));
                *(uint32_t*)(smem + OFF_X + o1) = pk2(f2h(v2), f2h(v3));
            }
        }
        __syncthreads();

        // GEMM2: K = 128
        gemm_strip<8>(x, w1, wrow, wcol, lm, acc);

        // epilogue 2: relu(acc+b1) -> scatter atomicMax (values >= 0)
#pragma unroll
        for (int m = 0; m < 2; m++) {
            const int r0 = wrow + m * 16 + g;
            const int e0 = cs[r0], e1 = cs[r0 + 8];
#pragma unroll
            for (int n = 0; n < 4; n++) {
                const int col = wcol + n * 8 + t * 2;
                const float bx = b1s[col], by = b1s[col + 1];
                if (e0 >= 0) {
                    float v0 = acc[m][n][0] + bx;
                    float v1 = acc[m][n][1] + by;
                    float* dst = &g_tmp[(size_t)e0 * PAIR + col];
                    if (v0 > 0.f) atomicMax((int*)&dst[0], __float_as_int(v0));
                    if (v1 > 0.f) atomicMax((int*)&dst[1], __float_as_int(v1));
                }
                if (e1 >= 0) {
                    float v2 = acc[m][n][2] + bx;
                    float v3 = acc[m][n][3] + by;
                    float* dst = &g_tmp[(size_t)e1 * PAIR + col];
                    if (v2 > 0.f) atomicMax((int*)&dst[0], __float_as_int(v2));
                    if (v3 > 0.f) atomicMax((int*)&dst[1], __float_as_int(v3));
                }
            }
        }
    }
}

// ---------------------------------------------------------------------------
// Kernel 3: node MLP, 64-node tiles, 256 threads, per-layer weight staging.
// ---------------------------------------------------------------------------
#define NTS 64
#define ACT_LD 132
#define NODE_SMEM_BYTES ((NTS*ACT_LD + PAIR*PAIR) * 4)

__global__ __launch_bounds__(TPB, 1)
void node_kernel(const float* __restrict__ infeats,
                 const float* __restrict__ Wa, const float* __restrict__ ba,
                 const float* __restrict__ Wb, const float* __restrict__ bb_,
                 const float* __restrict__ W2, const float* __restrict__ b2,
                 float* __restrict__ out, int N) {
    extern __shared__ float smemf[];
    float* acts = smemf;                 // 64 x 132
    float* Ws   = smemf + NTS * ACT_LD;  // 128 x 128

    const int tid = threadIdx.x;
    const int base = blockIdx.x * NTS;
    const int nvalid = min(NTS, N - base);

    for (int idx = tid; idx < NTS * (PAIR / 4); idx += TPB) {
        int node = idx >> 5, k = (idx & 31) * 4;
        float4 v = make_float4(0.f, 0.f, 0.f, 0.f);
        if (node < nvalid) v = *(const float4*)&g_tmp[(size_t)(base + node) * PAIR + k];
        *(float4*)&acts[node * ACT_LD + k] = v;
    }

    const int tx = tid & 15, ty = tid >> 4;
    const int col0 = tx * 8, row0 = ty * 4;

    const float* Wp[3] = {Wa, Wb, W2};
    const float* bp[3] = {ba, bb_, b2};

    for (int layer = 0; layer < 3; layer++) {
        __syncthreads();
        for (int i = tid * 4; i < PAIR * PAIR; i += TPB * 4)
            *(float4*)&Ws[i] = *(const float4*)&Wp[layer][i];
        __syncthreads();

        float acc[4][8];
#pragma unroll
        for (int r = 0; r < 4; r++)
#pragma unroll
            for (int c = 0; c < 8; c++) acc[r][c] = 0.f;

        for (int k = 0; k < PAIR; k += 4) {
            float4 a[4];
#pragma unroll
            for (int r = 0; r < 4; r++)
                a[r] = *(float4*)&acts[(row0 + r) * ACT_LD + k];
#pragma unroll
            for (int kk = 0; kk < 4; kk++) {
                float4 w0 = *(float4*)&Ws[(k + kk) * PAIR + col0];
                float4 w1 = *(float4*)&Ws[(k + kk) * PAIR + col0 + 4];
                float b[8] = {w0.x, w0.y, w0.z, w0.w, w1.x, w1.y, w1.z, w1.w};
#pragma unroll
                for (int r = 0; r < 4; r++) {
                    float av = (kk == 0) ? a[r].x : (kk == 1) ? a[r].y
                             : (kk == 2) ? a[r].z : a[r].w;
#pragma unroll
                    for (int c = 0; c < 8; c++) acc[r][c] += av * b[c];
                }
            }
        }
        __syncthreads();

        float bias[8];
#pragma unroll
        for (int c = 0; c < 8; c++) bias[c] = bp[layer][col0 + c];

        if (layer < 2) {
#pragma unroll
            for (int r = 0; r < 4; r++) {
                float4 v0, v1;
                v0.x = fmaxf(acc[r][0] + bias[0], 0.f);
                v0.y = fmaxf(acc[r][1] + bias[1], 0.f);
                v0.z = fmaxf(acc[r][2] + bias[2], 0.f);
                v0.w = fmaxf(acc[r][3] + bias[3], 0.f);
                v1.x = fmaxf(acc[r][4] + bias[4], 0.f);
                v1.y = fmaxf(acc[r][5] + bias[5], 0.f);
                v1.z = fmaxf(acc[r][6] + bias[6], 0.f);
                v1.w = fmaxf(acc[r][7] + bias[7], 0.f);
                *(float4*)&acts[(row0 + r) * ACT_LD + col0]     = v0;
                *(float4*)&acts[(row0 + r) * ACT_LD + col0 + 4] = v1;
            }
        } else {
#pragma unroll
            for (int r = 0; r < 4; r++) {
                int node = row0 + r;
                if (node < nvalid) {
                    const float* inrow = &infeats[(size_t)(base + node) * SC + col0];
                    float* orow = &out[(size_t)(base + node) * SC + col0];
                    float4 i0 = *(const float4*)&inrow[0];
                    float4 i1 = *(const float4*)&inrow[4];
                    float4 v0, v1;
                    v0.x = fmaxf(acc[r][0] + bias[0] + i0.x, 0.f);
                    v0.y = fmaxf(acc[r][1] + bias[1] + i0.y, 0.f);
                    v0.z = fmaxf(acc[r][2] + bias[2] + i0.z, 0.f);
                    v0.w = fmaxf(acc[r][3] + bias[3] + i0.w, 0.f);
                    v1.x = fmaxf(acc[r][4] + bias[4] + i1.x, 0.f);
                    v1.y = fmaxf(acc[r][5] + bias[5] + i1.y, 0.f);
                    v1.z = fmaxf(acc[r][6] + bias[6] + i1.z, 0.f);
                    v1.w = fmaxf(acc[r][7] + bias[7] + i1.w, 0.f);
                    *(float4*)&orow[0] = v0;
                    *(float4*)&orow[4] = v1;
                }
            }
        }
    }
}

// ---------------------------------------------------------------------------
extern "C" void kernel_launch(void* const* d_in, const int* in_sizes, int n_in,
                              void* d_out, int out_size) {
    const float* infeats = (const float*)d_in[0];
    const float* pw      = (const float*)d_in[1];
    const int*   c_idxs  = (const int*)d_in[2];
    const int*   n_idxs  = (const int*)d_in[3];
    const float* W_rd  = (const float*)d_in[5];
    const float* b_rd  = (const float*)d_in[6];
    const float* W_pw0 = (const float*)d_in[7];
    const float* b_pw0 = (const float*)d_in[8];
    const float* W_pw1 = (const float*)d_in[9];
    const float* b_pw1 = (const float*)d_in[10];
    const float* W_f1a = (const float*)d_in[11];
    const float* b_f1a = (const float*)d_in[12];
    const float* W_f1b = (const float*)d_in[13];
    const float* b_f1b = (const float*)d_in[14];
    const float* W_f2  = (const float*)d_in[15];
    const float* b_f2  = (const float*)d_in[16];
    float* out = (float*)d_out;

    const int N = in_sizes[0] / SC;
    const int E = in_sizes[1] / PWN;

    cudaFuncSetAttribute(edge_kernel, cudaFuncAttributeMaxDynamicSharedMemorySize,
                         EDGE_SMEM_BYTES);
    cudaFuncSetAttribute(node_kernel, cudaFuncAttributeMaxDynamicSharedMemorySize,
                         NODE_SMEM_BYTES);

    const int tot = N * PAIR;
    clear_accum_kernel<<<(tot + 255) / 256, 256>>>(tot);

    reduce_kernel<<<(N + 7) / 8, TPB>>>(infeats, W_rd, b_rd, N);

    const int ntiles = (E + TS - 1) / TS;
    const int grid = ntiles < 148 ? ntiles : 148;
    edge_kernel<<<grid, ETPB, EDGE_SMEM_BYTES>>>(pw, c_idxs, n_idxs,
                                                 W_pw0, b_pw0, W_pw1, b_pw1,
                                                 E, ntiles);

    node_kernel<<<(N + NTS - 1) / NTS, TPB, NODE_SMEM_BYTES>>>(
        infeats, W_f1a, b_f1a, W_f1b, b_f1b, W_f2, b_f2, out, N);
}